// round 5
// baseline (speedup 1.0000x reference)
#include <cuda_runtime.h>
#include <math.h>

#define BB 64
#define SSEQ 256
#define HH 768
#define H4 3072
#define D2 1536
#define NSTEP 255
#define SLOT_S 514
#define SLOT_W 257

// ---------------- static device scratch (allocation-free rule) ----------------
__device__ float g_xg_f[(size_t)BB*SSEQ*H4];
__device__ float g_xg_b[(size_t)BB*SSEQ*H4];
__device__ float g_lstm_out[(size_t)BB*SSEQ*D2];
__device__ float g_dec_xg[(size_t)BB*NSTEP*H4];
__device__ float g_sh[(size_t)BB*SLOT_S*HH];
__device__ float g_sc[(size_t)BB*SLOT_S*HH];
__device__ float g_wh[(size_t)BB*SLOT_W*HH];
__device__ float g_wc[(size_t)BB*SLOT_W*HH];
__device__ float g_u[(size_t)BB*D2];
__device__ float g_wh1[(size_t)BB*NSTEP*HH];
__device__ float g_hst[2][2][BB*HH];
__device__ float g_cst[2][2][BB*HH];
__device__ int   g_sp[BB*NSTEP];
__device__ int   g_wp[BB*NSTEP];

__device__ __forceinline__ float sigf(float x) { return 1.0f / (1.0f + expf(-x)); }

// ---------------- zero stacks / states ----------------
__global__ void zero_kernel()
{
    size_t tid = (size_t)blockIdx.x * blockDim.x + threadIdx.x;
    size_t stride = (size_t)gridDim.x * blockDim.x;
    float4 z = make_float4(0.f, 0.f, 0.f, 0.f);
#define ZL(p, n) for (size_t i = tid; i < (size_t)(n) / 4; i += stride) ((float4*)(p))[i] = z;
    ZL(g_sh, (size_t)BB*SLOT_S*HH)
    ZL(g_sc, (size_t)BB*SLOT_S*HH)
    ZL(g_wh, (size_t)BB*SLOT_W*HH)
    ZL(g_wc, (size_t)BB*SLOT_W*HH)
    ZL(&g_hst[0][0][0], 2*2*BB*HH)
    ZL(&g_cst[0][0][0], 2*2*BB*HH)
#undef ZL
}

// ---------------- sp/wp trajectory scan (pure function of golds) ----------------
__global__ void scan_kernel(const int* __restrict__ golds)
{
    int b = threadIdx.x;
    if (b >= BB) return;
    int sp = 0, wp = 0;
    for (int t = 0; t < NSTEP; t++) {
        g_sp[b*NSTEP + t] = sp;
        g_wp[b*NSTEP + t] = wp;
        int g = golds[b*SSEQ + t + 1];
        sp += (g == 0) ? 1 : 2;
        wp += (g == 0) ? 0 : 1;
    }
}

// ---------------- big parallel GEMM: C[m,n] = bias[n] + A(row(m),:)·W(n,:) ----------------
// row(m) = (m / m_inner)*chunk_stride + (m % m_inner)*K  (strided A views)
__global__ __launch_bounds__(256) void gemm128(
    const float* __restrict__ A, const float* __restrict__ W,
    const float* __restrict__ bias, float* __restrict__ C,
    int M, int N, int K, int m_inner, long chunk_stride)
{
    __shared__ __align__(16) float As[16][132];
    __shared__ __align__(16) float Ws[16][132];
    int tid = threadIdx.x;
    int m0 = blockIdx.y * 128, n0 = blockIdx.x * 128;
    int lr = tid >> 1;
    int lk = (tid & 1) << 3;
    int m = m0 + lr; if (m >= M) m = M - 1;
    const float* arow = A + (size_t)(m / m_inner) * (size_t)chunk_stride
                          + (size_t)(m % m_inner) * (size_t)K;
    const float* wrow = W + (size_t)(n0 + lr) * (size_t)K;
    int tm = (tid & 15) << 3;
    int tn = (tid >> 4) << 3;
    float acc[8][8];
    #pragma unroll
    for (int i = 0; i < 8; i++)
        #pragma unroll
        for (int j = 0; j < 8; j++) acc[i][j] = 0.0f;

    for (int k0 = 0; k0 < K; k0 += 16) {
        #pragma unroll
        for (int q = 0; q < 2; q++) {
            float4 a = *(const float4*)(arow + k0 + lk + q*4);
            As[lk+q*4+0][lr]=a.x; As[lk+q*4+1][lr]=a.y; As[lk+q*4+2][lr]=a.z; As[lk+q*4+3][lr]=a.w;
            float4 w = *(const float4*)(wrow + k0 + lk + q*4);
            Ws[lk+q*4+0][lr]=w.x; Ws[lk+q*4+1][lr]=w.y; Ws[lk+q*4+2][lr]=w.z; Ws[lk+q*4+3][lr]=w.w;
        }
        __syncthreads();
        #pragma unroll
        for (int kk = 0; kk < 16; kk++) {
            float ar[8], wr[8];
            *(float4*)&ar[0] = *(const float4*)&As[kk][tm];
            *(float4*)&ar[4] = *(const float4*)&As[kk][tm+4];
            *(float4*)&wr[0] = *(const float4*)&Ws[kk][tn];
            *(float4*)&wr[4] = *(const float4*)&Ws[kk][tn+4];
            #pragma unroll
            for (int i = 0; i < 8; i++)
                #pragma unroll
                for (int j = 0; j < 8; j++) acc[i][j] += ar[i] * wr[j];
        }
        __syncthreads();
    }
    #pragma unroll
    for (int i = 0; i < 8; i++) {
        int mm = m0 + tm + i;
        if (mm < M) {
            #pragma unroll
            for (int j = 0; j < 8; j++) {
                int nn = n0 + tn + j;
                C[(size_t)mm * N + nn] = acc[i][j] + bias[nn];
            }
        }
    }
}

// ---------------- recurrent cell machinery ----------------
struct CellSmem {
    float Hs[2][16][68];
    float Wsm[2][16][36];
    float Red[128][16];
    int   aoffA[64];
    int   aoffB[64];
};

// acc[i][g] += A(aoff[b], k) · W(g*768 + j0+jj, k), k in [0,K). K-chunks split by group.
__device__ __forceinline__ void cell_accum(
    float acc[4][4], const float* __restrict__ A, const int* __restrict__ aoff,
    const float* __restrict__ W, int K, int j0, int tid128, int group,
    float Hs[16][68], float Wsm[16][36])
{
    int jj = tid128 & 7, bq = tid128 >> 3;
    int nch = K >> 4;
    for (int c = group; c < nch; c += 2) {
        int k0 = c << 4;
        #pragma unroll
        for (int q = 0; q < 2; q++) {
            int idx = tid128 * 2 + q;
            int row = idx >> 2, kq = idx & 3;
            float4 v = *(const float4*)(A + (size_t)aoff[row] + k0 + kq*4);
            Hs[kq*4+0][row]=v.x; Hs[kq*4+1][row]=v.y; Hs[kq*4+2][row]=v.z; Hs[kq*4+3][row]=v.w;
        }
        {
            int col = tid128 >> 2, kq = tid128 & 3;
            int jjw = col >> 2, gw = col & 3;
            float4 v = *(const float4*)(W + (size_t)(gw*HH + j0 + jjw)*K + k0 + kq*4);
            Wsm[kq*4+0][col]=v.x; Wsm[kq*4+1][col]=v.y; Wsm[kq*4+2][col]=v.z; Wsm[kq*4+3][col]=v.w;
        }
        asm volatile("bar.sync %0, 128;" :: "r"(group+1) : "memory");
        #pragma unroll
        for (int kk = 0; kk < 16; kk++) {
            float4 av = *(const float4*)&Hs[kk][bq*4];
            float4 wv = *(const float4*)&Wsm[kk][jj*4];
            float a0=av.x, a1=av.y, a2=av.z, a3=av.w;
            float w0=wv.x, w1=wv.y, w2=wv.z, w3=wv.w;
            acc[0][0]+=a0*w0; acc[0][1]+=a0*w1; acc[0][2]+=a0*w2; acc[0][3]+=a0*w3;
            acc[1][0]+=a1*w0; acc[1][1]+=a1*w1; acc[1][2]+=a1*w2; acc[1][3]+=a1*w3;
            acc[2][0]+=a2*w0; acc[2][1]+=a2*w1; acc[2][2]+=a2*w2; acc[2][3]+=a2*w3;
            acc[3][0]+=a3*w0; acc[3][1]+=a3*w1; acc[3][2]+=a3*w2; acc[3][3]+=a3*w3;
        }
        asm volatile("bar.sync %0, 128;" :: "r"(group+1) : "memory");
    }
}

// ---------------- BiLSTM step: grid (96, 2) : 8 j per block x 2 directions ----------------
__global__ __launch_bounds__(256) void bilstm_step(
    const float* __restrict__ Whh_f, const float* __restrict__ Whh_b, int t)
{
    __shared__ CellSmem sm;
    int d = blockIdx.y;
    int tid = threadIdx.x, group = tid >> 7, tid128 = tid & 127;
    int jj = tid128 & 7, bq = tid128 >> 3;
    int j0 = blockIdx.x * 8, j = j0 + jj;
    int cur = t & 1, nxt = cur ^ 1;
    int tt = d ? (SSEQ - 1 - t) : t;
    const float* Hprev = g_hst[d][cur];
    const float* Cprev = g_cst[d][cur];
    const float* pre   = d ? g_xg_b : g_xg_f;
    const float* W     = d ? Whh_b : Whh_f;
    if (tid < 64) sm.aoffA[tid] = tid * HH;
    float acc[4][4];
    #pragma unroll
    for (int i = 0; i < 4; i++)
        #pragma unroll
        for (int g = 0; g < 4; g++)
            acc[i][g] = (group == 0)
                ? pre[((size_t)(bq*4+i)*SSEQ + tt)*H4 + g*HH + j] : 0.0f;
    __syncthreads();
    cell_accum(acc, Hprev, sm.aoffA, W, HH, j0, tid128, group, sm.Hs[group], sm.Wsm[group]);
    __syncthreads();
    if (group) {
        #pragma unroll
        for (int i = 0; i < 4; i++)
            #pragma unroll
            for (int g = 0; g < 4; g++) sm.Red[tid128][i*4+g] = acc[i][g];
    }
    __syncthreads();
    if (!group) {
        #pragma unroll
        for (int i = 0; i < 4; i++) {
            int b = bq*4 + i;
            float gi = acc[i][0] + sm.Red[tid128][i*4+0];
            float gf = acc[i][1] + sm.Red[tid128][i*4+1];
            float gg = acc[i][2] + sm.Red[tid128][i*4+2];
            float go = acc[i][3] + sm.Red[tid128][i*4+3];
            float cp = Cprev[b*HH + j];
            float c1 = sigf(gf)*cp + sigf(gi)*tanhf(gg);
            float h1 = sigf(go)*tanhf(c1);
            g_hst[d][nxt][b*HH + j] = h1;
            g_cst[d][nxt][b*HH + j] = c1;
            g_lstm_out[((size_t)b*SSEQ + tt)*D2 + d*HH + j] = h1;
        }
    }
}

// ---------------- decode: subword cell ----------------
__global__ __launch_bounds__(256) void subw_step(const float* __restrict__ Whh, int t)
{
    __shared__ CellSmem sm;
    int tid = threadIdx.x, group = tid >> 7, tid128 = tid & 127;
    int jj = tid128 & 7, bq = tid128 >> 3;
    int j0 = blockIdx.x * 8, j = j0 + jj;
    if (tid < 64) sm.aoffA[tid] = (tid*SLOT_S + g_sp[tid*NSTEP + t]) * HH;
    float acc[4][4];
    #pragma unroll
    for (int i = 0; i < 4; i++)
        #pragma unroll
        for (int g = 0; g < 4; g++)
            acc[i][g] = (group == 0)
                ? g_dec_xg[((size_t)(bq*4+i)*NSTEP + t)*H4 + g*HH + j] : 0.0f;
    __syncthreads();
    cell_accum(acc, g_sh, sm.aoffA, Whh, HH, j0, tid128, group, sm.Hs[group], sm.Wsm[group]);
    __syncthreads();
    if (group) {
        #pragma unroll
        for (int i = 0; i < 4; i++)
            #pragma unroll
            for (int g = 0; g < 4; g++) sm.Red[tid128][i*4+g] = acc[i][g];
    }
    __syncthreads();
    if (!group) {
        #pragma unroll
        for (int i = 0; i < 4; i++) {
            int b = bq*4 + i;
            int sp = g_sp[b*NSTEP + t];
            float gi = acc[i][0] + sm.Red[tid128][i*4+0];
            float gf = acc[i][1] + sm.Red[tid128][i*4+1];
            float gg = acc[i][2] + sm.Red[tid128][i*4+2];
            float go = acc[i][3] + sm.Red[tid128][i*4+3];
            float cp = g_sc[((size_t)b*SLOT_S + sp)*HH + j];
            float c1 = sigf(gf)*cp + sigf(gi)*tanhf(gg);
            float h1 = sigf(go)*tanhf(c1);
            g_sh[((size_t)b*SLOT_S + sp + 1)*HH + j] = h1;
            g_sc[((size_t)b*SLOT_S + sp + 1)*HH + j] = c1;
            g_u[(size_t)b*D2 + j]      = h1;
            g_u[(size_t)b*D2 + HH + j] = c1;
        }
    }
}

// ---------------- decode: word cell ----------------
__global__ __launch_bounds__(256) void word_step(
    const float* __restrict__ Wih, const float* __restrict__ Whh,
    const float* __restrict__ bvec, int t)
{
    __shared__ CellSmem sm;
    int tid = threadIdx.x, group = tid >> 7, tid128 = tid & 127;
    int jj = tid128 & 7, bq = tid128 >> 3;
    int j0 = blockIdx.x * 8, j = j0 + jj;
    if (tid < 64) {
        sm.aoffA[tid] = tid * D2;
        sm.aoffB[tid] = (tid*SLOT_W + g_wp[tid*NSTEP + t]) * HH;
    }
    float acc[4][4];
    #pragma unroll
    for (int i = 0; i < 4; i++)
        #pragma unroll
        for (int g = 0; g < 4; g++)
            acc[i][g] = (group == 0) ? bvec[g*HH + j] : 0.0f;
    __syncthreads();
    cell_accum(acc, g_u,  sm.aoffA, Wih, D2, j0, tid128, group, sm.Hs[group], sm.Wsm[group]);
    cell_accum(acc, g_wh, sm.aoffB, Whh, HH, j0, tid128, group, sm.Hs[group], sm.Wsm[group]);
    __syncthreads();
    if (group) {
        #pragma unroll
        for (int i = 0; i < 4; i++)
            #pragma unroll
            for (int g = 0; g < 4; g++) sm.Red[tid128][i*4+g] = acc[i][g];
    }
    __syncthreads();
    if (!group) {
        #pragma unroll
        for (int i = 0; i < 4; i++) {
            int b = bq*4 + i;
            int wp = g_wp[b*NSTEP + t];
            float gi = acc[i][0] + sm.Red[tid128][i*4+0];
            float gf = acc[i][1] + sm.Red[tid128][i*4+1];
            float gg = acc[i][2] + sm.Red[tid128][i*4+2];
            float go = acc[i][3] + sm.Red[tid128][i*4+3];
            float cp = g_wc[((size_t)b*SLOT_W + wp)*HH + j];
            float c1 = sigf(gf)*cp + sigf(gi)*tanhf(gg);
            float h1 = sigf(go)*tanhf(c1);
            g_wh[((size_t)b*SLOT_W + wp + 1)*HH + j] = h1;
            g_wc[((size_t)b*SLOT_W + wp + 1)*HH + j] = c1;
            g_wh1[((size_t)b*NSTEP + t)*HH + j] = h1;
        }
    }
}

// ---------------- final classifier ----------------
__global__ void logits_kernel(const float* __restrict__ clsW,
                              const float* __restrict__ clsb,
                              float* __restrict__ out)
{
    int gw = (int)((blockIdx.x * blockDim.x + threadIdx.x) >> 5);
    int lane = threadIdx.x & 31;
    if (gw >= BB*NSTEP) return;
    int b = gw / NSTEP, t = gw % NSTEP;
    const float* wh1 = g_wh1 + ((size_t)b*NSTEP + t)*HH;
    const float* xc  = g_lstm_out + ((size_t)b*SSEQ + t + 1)*D2;
    float s0 = 0.f, s1 = 0.f;
    for (int k = lane; k < HH; k += 32) {
        float v = wh1[k];
        s0 += v * clsW[k];
        s1 += v * clsW[2304 + k];
    }
    for (int k = lane; k < D2; k += 32) {
        float v = xc[k];
        s0 += v * clsW[HH + k];
        s1 += v * clsW[2304 + HH + k];
    }
    #pragma unroll
    for (int o = 16; o; o >>= 1) {
        s0 += __shfl_xor_sync(0xffffffffu, s0, o);
        s1 += __shfl_xor_sync(0xffffffffu, s1, o);
    }
    size_t base = ((size_t)b*SSEQ + t + 1) * 2;
    if (lane == 0) out[base + 0] = s0 + clsb[0];
    if (lane == 1) out[base + 1] = s1 + clsb[1];
    if (t == 0) {
        if (lane == 2) out[(size_t)b*SSEQ*2 + 0] = -1.0f;
        if (lane == 3) out[(size_t)b*SSEQ*2 + 1] =  1.0f;
    }
}

// ---------------- host launch ----------------
extern "C" void kernel_launch(void* const* d_in, const int* in_sizes, int n_in,
                              void* d_out, int out_size)
{
    // locate golds (only input with B*S = 16384 elements); others keep dict order
    int gi = -1;
    for (int i = 0; i < n_in; i++) if (in_sizes[i] == BB*SSEQ) gi = i;
    const float* P[15]; int p = 0;
    const int* golds = nullptr;
    for (int i = 0; i < n_in; i++) {
        if (i == gi) golds = (const int*)d_in[i];
        else if (p < 15) P[p++] = (const float*)d_in[i];
    }
    const float* hidden = P[0];
    const float *Wih_f = P[1], *Whh_f = P[2], *b_f = P[3];
    const float *Wih_b = P[4], *Whh_b = P[5], *b_b = P[6];
    const float *sWih = P[7], *sWhh = P[8], *sb = P[9];
    const float *wWih = P[10], *wWhh = P[11], *wb = P[12];
    const float *clsW = P[13], *clsb = P[14];
    float* out = (float*)d_out;

    void *xf, *xb, *lo, *dxg;
    cudaGetSymbolAddress(&xf,  g_xg_f);
    cudaGetSymbolAddress(&xb,  g_xg_b);
    cudaGetSymbolAddress(&lo,  g_lstm_out);
    cudaGetSymbolAddress(&dxg, g_dec_xg);

    zero_kernel<<<512, 256>>>();
    scan_kernel<<<1, 64>>>(golds);

    // x-projections for both BiLSTM directions
    gemm128<<<dim3(24, 128), 256>>>(hidden, Wih_f, b_f, (float*)xf,
                                    BB*SSEQ, H4, HH, BB*SSEQ, 0);
    gemm128<<<dim3(24, 128), 256>>>(hidden, Wih_b, b_b, (float*)xb,
                                    BB*SSEQ, H4, HH, BB*SSEQ, 0);

    for (int t = 0; t < SSEQ; t++)
        bilstm_step<<<dim3(96, 2), 256>>>(Whh_f, Whh_b, t);

    // decode x-projection: x_prev = lstm_out[:, :-1, :] (strided rows)
    gemm128<<<dim3(24, 128), 256>>>((const float*)lo, sWih, sb, (float*)dxg,
                                    BB*NSTEP, H4, D2, NSTEP, (long)SSEQ*D2);

    for (int t = 0; t < NSTEP; t++) {
        subw_step<<<96, 256>>>(sWhh, t);
        word_step<<<96, 256>>>(wWih, wWhh, wb, t);
    }

    logits_kernel<<<(BB*NSTEP + 7) / 8, 256>>>(clsW, clsb, out);
}

// round 7
// speedup vs baseline: 1.2604x; 1.2604x over previous
#include <cuda_runtime.h>
#include <math.h>

#define BB 64
#define SSEQ 256
#define HH 768
#define H4 3072
#define D2 1536
#define NSTEP 255
#define SLOT_S 514
#define SLOT_W 257

// ---------------- static device scratch (allocation-free rule) ----------------
__device__ float g_xg_f[(size_t)BB*SSEQ*H4];
__device__ float g_xg_b[(size_t)BB*SSEQ*H4];
__device__ float g_lstm_out[(size_t)BB*SSEQ*D2];
__device__ float g_dec_xg[(size_t)BB*NSTEP*H4];
__device__ float g_sh[(size_t)BB*SLOT_S*HH];
__device__ float g_sc[(size_t)BB*SLOT_S*HH];
__device__ float g_wh[(size_t)BB*SLOT_W*HH];
__device__ float g_wc[(size_t)BB*SLOT_W*HH];
__device__ float g_u[(size_t)BB*D2];
__device__ float g_wh1[(size_t)BB*NSTEP*HH];
__device__ float g_hst[2][2][BB*HH];
__device__ float g_cst[2][2][BB*HH];
__device__ int   g_sp[BB*NSTEP];
__device__ int   g_wp[BB*NSTEP];

__device__ __forceinline__ float sigf(float x) { return 1.0f / (1.0f + expf(-x)); }

// ---------------- zero stacks / states ----------------
__global__ void zero_kernel()
{
    size_t tid = (size_t)blockIdx.x * blockDim.x + threadIdx.x;
    size_t stride = (size_t)gridDim.x * blockDim.x;
    float4 z = make_float4(0.f, 0.f, 0.f, 0.f);
#define ZL(p, n) for (size_t i = tid; i < (size_t)(n) / 4; i += stride) ((float4*)(p))[i] = z;
    ZL(g_sh, (size_t)BB*SLOT_S*HH)
    ZL(g_sc, (size_t)BB*SLOT_S*HH)
    ZL(g_wh, (size_t)BB*SLOT_W*HH)
    ZL(g_wc, (size_t)BB*SLOT_W*HH)
    ZL(&g_hst[0][0][0], 2*2*BB*HH)
    ZL(&g_cst[0][0][0], 2*2*BB*HH)
#undef ZL
}

// ---------------- sp/wp trajectory scan (pure function of golds) ----------------
__global__ void scan_kernel(const int* __restrict__ golds)
{
    int b = threadIdx.x;
    if (b >= BB) return;
    int sp = 0, wp = 0;
    for (int t = 0; t < NSTEP; t++) {
        g_sp[b*NSTEP + t] = sp;
        g_wp[b*NSTEP + t] = wp;
        int g = golds[b*SSEQ + t + 1];
        sp += (g == 0) ? 1 : 2;
        wp += (g == 0) ? 0 : 1;
    }
}

// ---------------- big parallel GEMM: C[m,n] = bias[n] + A(row(m),:)·W(n,:) ----------------
// Conflict-free microtile: thread covers rows {tm4..tm4+3, tm4+64..tm4+67},
// cols {tn4..tn4+3, tn4+64..tn4+67}; lane addresses are contiguous float4s.
__global__ __launch_bounds__(256) void gemm128(
    const float* __restrict__ A, const float* __restrict__ W,
    const float* __restrict__ bias, float* __restrict__ C,
    int M, int N, int K, int m_inner, long chunk_stride)
{
    __shared__ __align__(16) float As[16][132];
    __shared__ __align__(16) float Ws[16][132];
    int tid = threadIdx.x;
    int m0 = blockIdx.y * 128, n0 = blockIdx.x * 128;
    int lr = tid >> 1;
    int lk = (tid & 1) << 3;
    int m = m0 + lr; if (m >= M) m = M - 1;
    const float* arow = A + (size_t)(m / m_inner) * (size_t)chunk_stride
                          + (size_t)(m % m_inner) * (size_t)K;
    const float* wrow = W + (size_t)(n0 + lr) * (size_t)K;
    int tm4 = (tid & 15) << 2;
    int tn4 = (tid >> 4) << 2;
    float acc[8][8];
    #pragma unroll
    for (int i = 0; i < 8; i++)
        #pragma unroll
        for (int j = 0; j < 8; j++) acc[i][j] = 0.0f;

    for (int k0 = 0; k0 < K; k0 += 16) {
        #pragma unroll
        for (int q = 0; q < 2; q++) {
            float4 a = *(const float4*)(arow + k0 + lk + q*4);
            As[lk+q*4+0][lr]=a.x; As[lk+q*4+1][lr]=a.y; As[lk+q*4+2][lr]=a.z; As[lk+q*4+3][lr]=a.w;
            float4 w = *(const float4*)(wrow + k0 + lk + q*4);
            Ws[lk+q*4+0][lr]=w.x; Ws[lk+q*4+1][lr]=w.y; Ws[lk+q*4+2][lr]=w.z; Ws[lk+q*4+3][lr]=w.w;
        }
        __syncthreads();
        #pragma unroll
        for (int kk = 0; kk < 16; kk++) {
            float ar[8], wr[8];
            *(float4*)&ar[0] = *(const float4*)&As[kk][tm4];
            *(float4*)&ar[4] = *(const float4*)&As[kk][tm4 + 64];
            *(float4*)&wr[0] = *(const float4*)&Ws[kk][tn4];
            *(float4*)&wr[4] = *(const float4*)&Ws[kk][tn4 + 64];
            #pragma unroll
            for (int i = 0; i < 8; i++)
                #pragma unroll
                for (int j = 0; j < 8; j++) acc[i][j] += ar[i] * wr[j];
        }
        __syncthreads();
    }
    #pragma unroll
    for (int i = 0; i < 8; i++) {
        int mm = m0 + ((i < 4) ? (tm4 + i) : (64 + tm4 + i - 4));
        if (mm < M) {
            #pragma unroll
            for (int j = 0; j < 8; j++) {
                int nn = n0 + ((j < 4) ? (tn4 + j) : (64 + tn4 + j - 4));
                C[(size_t)mm * N + nn] = acc[i][j] + bias[nn];
            }
        }
    }
}

// ---------------- recurrent cell machinery (v2: broadcast layout) ----------------
// Block: 256 threads = 2 K-groups x 128. Group thread: wi = t&7, bq = t>>3.
// Columns: NCOL = 4*JT (gates x j-tile); col = c*8 + wi, c < CPT = JT/2.
// Per-thread microtile: 4 batches x CPT columns.
struct CellSmem2 {
    float As[2][16][68];      // [group][kk][batch] (stride 68: 16B-aligned rows)
    float Wsm[2][16][8][8];   // [group][kk][wi][c]
    float Red[2][64][50];     // [group][batch][col]  (stride 50: conflict-free)
    int   aoffA[64];
    int   aoffB[64];
};

template<int JT>
__device__ __forceinline__ void cell_accum2(
    float (&acc)[4][JT/2],
    const float* __restrict__ A, const int* __restrict__ aoff,
    const float* __restrict__ W, int K, int j0,
    int tid128, int group,
    float (&As)[16][68], float (&Wsm)[16][8][8])
{
    constexpr int CPT = JT/2;
    constexpr int NCOL = 4*JT;
    int wi = tid128 & 7, bq = tid128 >> 3;
    int b2 = tid128 >> 1, half = tid128 & 1;
    int nch = K >> 4;
    for (int ch = group; ch < nch; ch += 2) {
        int k0 = ch << 4;
        {   // load A slab: 64 gathered rows x 16 k  -> As[kk][b]
            const float* src = A + (size_t)aoff[b2] + k0 + half*8;
            float4 v0 = *(const float4*)(src);
            float4 v1 = *(const float4*)(src + 4);
            int kb = half*8;
            As[kb+0][b2]=v0.x; As[kb+1][b2]=v0.y; As[kb+2][b2]=v0.z; As[kb+3][b2]=v0.w;
            As[kb+4][b2]=v1.x; As[kb+5][b2]=v1.y; As[kb+6][b2]=v1.z; As[kb+7][b2]=v1.w;
        }
        // load W slab: NCOL cols x 16 k -> Wsm[kk][wi][c]
        for (int idx = tid128; idx < NCOL*4; idx += 128) {
            int col = idx >> 2, kq = idx & 3;
            int c = col >> 3, wcol = col & 7;
            int gate = col / JT, jj = col - gate*JT;
            float4 v = *(const float4*)(W + (size_t)(gate*HH + j0 + jj)*K + k0 + kq*4);
            Wsm[kq*4+0][wcol][c]=v.x; Wsm[kq*4+1][wcol][c]=v.y;
            Wsm[kq*4+2][wcol][c]=v.z; Wsm[kq*4+3][wcol][c]=v.w;
        }
        asm volatile("bar.sync %0, 128;" :: "r"(group+1) : "memory");
        #pragma unroll
        for (int kk = 0; kk < 16; kk++) {
            float4 av = *(const float4*)&As[kk][bq*4];
            float a0=av.x, a1=av.y, a2=av.z, a3=av.w;
            float w[CPT];
            float4 wv0 = *(const float4*)&Wsm[kk][wi][0];
            if (CPT >= 1) w[0]=wv0.x;
            if (CPT >= 2) w[1]=wv0.y;
            if (CPT >= 3) w[2]=wv0.z;
            if (CPT >= 4) w[3]=wv0.w;
            if (CPT > 4) {
                float4 wv1 = *(const float4*)&Wsm[kk][wi][4];
                w[4]=wv1.x;
                if (CPT >= 6) w[5]=wv1.y;
            }
            #pragma unroll
            for (int c = 0; c < CPT; c++) {
                acc[0][c] += a0 * w[c];
                acc[1][c] += a1 * w[c];
                acc[2][c] += a2 * w[c];
                acc[3][c] += a3 * w[c];
            }
        }
        asm volatile("bar.sync %0, 128;" :: "r"(group+1) : "memory");
    }
}

template<int JT>
__device__ __forceinline__ void cell_store_red(
    float (&acc)[4][JT/2], float (&Red)[64][50], int tid128)
{
    constexpr int CPT = JT/2;
    int wi = tid128 & 7, bq = tid128 >> 3;
    #pragma unroll
    for (int i = 0; i < 4; i++)
        #pragma unroll
        for (int c = 0; c < CPT; c++)
            Red[bq*4 + i][c*8 + wi] = acc[i][c];
}

// ---------------- BiLSTM step: grid (64, 2), JT=12 ----------------
__global__ __launch_bounds__(256) void bilstm_step(
    const float* __restrict__ Whh_f, const float* __restrict__ Whh_b, int t)
{
    constexpr int JT = 12, CPT = JT/2;
    __shared__ CellSmem2 sm;
    int d = blockIdx.y;
    int tid = threadIdx.x, group = tid >> 7, tid128 = tid & 127;
    int wi = tid128 & 7, bq = tid128 >> 3;
    int j0 = blockIdx.x * JT;
    int cur = t & 1, nxt = cur ^ 1;
    int tt = d ? (SSEQ - 1 - t) : t;
    const float* Hprev = g_hst[d][cur];
    const float* Cprev = g_cst[d][cur];
    const float* pre   = d ? g_xg_b : g_xg_f;
    const float* W     = d ? Whh_b : Whh_f;
    if (tid < 64) sm.aoffA[tid] = tid * HH;
    float acc[4][CPT];
    #pragma unroll
    for (int i = 0; i < 4; i++)
        #pragma unroll
        for (int c = 0; c < CPT; c++) {
            if (group == 0) {
                int col = c*8 + wi;
                int gate = col / JT, jj = col - gate*JT;
                acc[i][c] = pre[((size_t)(bq*4+i)*SSEQ + tt)*H4 + gate*HH + j0 + jj];
            } else acc[i][c] = 0.0f;
        }
    __syncthreads();
    cell_accum2<JT>(acc, Hprev, sm.aoffA, W, HH, j0, tid128, group,
                    sm.As[group], sm.Wsm[group]);
    cell_store_red<JT>(acc, sm.Red[group], tid128);
    __syncthreads();
    for (int p = tid; p < 64*JT; p += 256) {
        int b = p / JT, jj = p - b*JT, j = j0 + jj;
        float gi = sm.Red[0][b][0*JT+jj] + sm.Red[1][b][0*JT+jj];
        float gf = sm.Red[0][b][1*JT+jj] + sm.Red[1][b][1*JT+jj];
        float gg = sm.Red[0][b][2*JT+jj] + sm.Red[1][b][2*JT+jj];
        float go = sm.Red[0][b][3*JT+jj] + sm.Red[1][b][3*JT+jj];
        float cp = Cprev[b*HH + j];
        float c1 = sigf(gf)*cp + sigf(gi)*tanhf(gg);
        float h1 = sigf(go)*tanhf(c1);
        g_hst[d][nxt][b*HH + j] = h1;
        g_cst[d][nxt][b*HH + j] = c1;
        g_lstm_out[((size_t)b*SSEQ + tt)*D2 + d*HH + j] = h1;
    }
}

// ---------------- decode: subword cell, grid 128, JT=6 ----------------
__global__ __launch_bounds__(256) void subw_step(const float* __restrict__ Whh, int t)
{
    constexpr int JT = 6, CPT = JT/2;
    __shared__ CellSmem2 sm;
    int tid = threadIdx.x, group = tid >> 7, tid128 = tid & 127;
    int wi = tid128 & 7, bq = tid128 >> 3;
    int j0 = blockIdx.x * JT;
    if (tid < 64) sm.aoffA[tid] = (tid*SLOT_S + g_sp[tid*NSTEP + t]) * HH;
    float acc[4][CPT];
    #pragma unroll
    for (int i = 0; i < 4; i++)
        #pragma unroll
        for (int c = 0; c < CPT; c++) {
            if (group == 0) {
                int col = c*8 + wi;
                int gate = col / JT, jj = col - gate*JT;
                acc[i][c] = g_dec_xg[((size_t)(bq*4+i)*NSTEP + t)*H4 + gate*HH + j0 + jj];
            } else acc[i][c] = 0.0f;
        }
    __syncthreads();
    cell_accum2<JT>(acc, g_sh, sm.aoffA, Whh, HH, j0, tid128, group,
                    sm.As[group], sm.Wsm[group]);
    cell_store_red<JT>(acc, sm.Red[group], tid128);
    __syncthreads();
    for (int p = tid; p < 64*JT; p += 256) {
        int b = p / JT, jj = p - b*JT, j = j0 + jj;
        int sp = g_sp[b*NSTEP + t];
        float gi = sm.Red[0][b][0*JT+jj] + sm.Red[1][b][0*JT+jj];
        float gf = sm.Red[0][b][1*JT+jj] + sm.Red[1][b][1*JT+jj];
        float gg = sm.Red[0][b][2*JT+jj] + sm.Red[1][b][2*JT+jj];
        float go = sm.Red[0][b][3*JT+jj] + sm.Red[1][b][3*JT+jj];
        float cp = g_sc[((size_t)b*SLOT_S + sp)*HH + j];
        float c1 = sigf(gf)*cp + sigf(gi)*tanhf(gg);
        float h1 = sigf(go)*tanhf(c1);
        g_sh[((size_t)b*SLOT_S + sp + 1)*HH + j] = h1;
        g_sc[((size_t)b*SLOT_S + sp + 1)*HH + j] = c1;
        g_u[(size_t)b*D2 + j]      = h1;
        g_u[(size_t)b*D2 + HH + j] = c1;
    }
}

// ---------------- decode: word cell, grid 128, JT=6 ----------------
__global__ __launch_bounds__(256) void word_step(
    const float* __restrict__ Wih, const float* __restrict__ Whh,
    const float* __restrict__ bvec, int t)
{
    constexpr int JT = 6, CPT = JT/2;
    __shared__ CellSmem2 sm;
    int tid = threadIdx.x, group = tid >> 7, tid128 = tid & 127;
    int wi = tid128 & 7, bq = tid128 >> 3;
    int j0 = blockIdx.x * JT;
    if (tid < 64) {
        sm.aoffA[tid] = tid * D2;
        sm.aoffB[tid] = (tid*SLOT_W + g_wp[tid*NSTEP + t]) * HH;
    }
    float acc[4][CPT];
    #pragma unroll
    for (int i = 0; i < 4; i++)
        #pragma unroll
        for (int c = 0; c < CPT; c++) {
            if (group == 0) {
                int col = c*8 + wi;
                int gate = col / JT, jj = col - gate*JT;
                acc[i][c] = bvec[gate*HH + j0 + jj];
            } else acc[i][c] = 0.0f;
        }
    __syncthreads();
    cell_accum2<JT>(acc, g_u,  sm.aoffA, Wih, D2, j0, tid128, group,
                    sm.As[group], sm.Wsm[group]);
    cell_accum2<JT>(acc, g_wh, sm.aoffB, Whh, HH, j0, tid128, group,
                    sm.As[group], sm.Wsm[group]);
    cell_store_red<JT>(acc, sm.Red[group], tid128);
    __syncthreads();
    for (int p = tid; p < 64*JT; p += 256) {
        int b = p / JT, jj = p - b*JT, j = j0 + jj;
        int wp = g_wp[b*NSTEP + t];
        float gi = sm.Red[0][b][0*JT+jj] + sm.Red[1][b][0*JT+jj];
        float gf = sm.Red[0][b][1*JT+jj] + sm.Red[1][b][1*JT+jj];
        float gg = sm.Red[0][b][2*JT+jj] + sm.Red[1][b][2*JT+jj];
        float go = sm.Red[0][b][3*JT+jj] + sm.Red[1][b][3*JT+jj];
        float cp = g_wc[((size_t)b*SLOT_W + wp)*HH + j];
        float c1 = sigf(gf)*cp + sigf(gi)*tanhf(gg);
        float h1 = sigf(go)*tanhf(c1);
        g_wh[((size_t)b*SLOT_W + wp + 1)*HH + j] = h1;
        g_wc[((size_t)b*SLOT_W + wp + 1)*HH + j] = c1;
        g_wh1[((size_t)b*NSTEP + t)*HH + j] = h1;
    }
}

// ---------------- final classifier ----------------
__global__ void logits_kernel(const float* __restrict__ clsW,
                              const float* __restrict__ clsb,
                              float* __restrict__ out)
{
    int gw = (int)((blockIdx.x * blockDim.x + threadIdx.x) >> 5);
    int lane = threadIdx.x & 31;
    if (gw >= BB*NSTEP) return;
    int b = gw / NSTEP, t = gw % NSTEP;
    const float* wh1 = g_wh1 + ((size_t)b*NSTEP + t)*HH;
    const float* xc  = g_lstm_out + ((size_t)b*SSEQ + t + 1)*D2;
    float s0 = 0.f, s1 = 0.f;
    for (int k = lane; k < HH; k += 32) {
        float v = wh1[k];
        s0 += v * clsW[k];
        s1 += v * clsW[2304 + k];
    }
    for (int k = lane; k < D2; k += 32) {
        float v = xc[k];
        s0 += v * clsW[HH + k];
        s1 += v * clsW[2304 + HH + k];
    }
    #pragma unroll
    for (int o = 16; o; o >>= 1) {
        s0 += __shfl_xor_sync(0xffffffffu, s0, o);
        s1 += __shfl_xor_sync(0xffffffffu, s1, o);
    }
    size_t base = ((size_t)b*SSEQ + t + 1) * 2;
    if (lane == 0) out[base + 0] = s0 + clsb[0];
    if (lane == 1) out[base + 1] = s1 + clsb[1];
    if (t == 0) {
        if (lane == 2) out[(size_t)b*SSEQ*2 + 0] = -1.0f;
        if (lane == 3) out[(size_t)b*SSEQ*2 + 1] =  1.0f;
    }
}

// ---------------- host launch ----------------
extern "C" void kernel_launch(void* const* d_in, const int* in_sizes, int n_in,
                              void* d_out, int out_size)
{
    // locate golds (only input with B*S = 16384 elements); others keep dict order
    int gi = -1;
    for (int i = 0; i < n_in; i++) if (in_sizes[i] == BB*SSEQ) gi = i;
    const float* P[15]; int p = 0;
    const int* golds = nullptr;
    for (int i = 0; i < n_in; i++) {
        if (i == gi) golds = (const int*)d_in[i];
        else if (p < 15) P[p++] = (const float*)d_in[i];
    }
    const float* hidden = P[0];
    const float *Wih_f = P[1], *Whh_f = P[2], *b_f = P[3];
    const float *Wih_b = P[4], *Whh_b = P[5], *b_b = P[6];
    const float *sWih = P[7], *sWhh = P[8], *sb = P[9];
    const float *wWih = P[10], *wWhh = P[11], *wb = P[12];
    const float *clsW = P[13], *clsb = P[14];
    float* out = (float*)d_out;

    void *xf, *xb, *lo, *dxg;
    cudaGetSymbolAddress(&xf,  g_xg_f);
    cudaGetSymbolAddress(&xb,  g_xg_b);
    cudaGetSymbolAddress(&lo,  g_lstm_out);
    cudaGetSymbolAddress(&dxg, g_dec_xg);

    zero_kernel<<<512, 256>>>();
    scan_kernel<<<1, 64>>>(golds);

    // x-projections for both BiLSTM directions
    gemm128<<<dim3(24, 128), 256>>>(hidden, Wih_f, b_f, (float*)xf,
                                    BB*SSEQ, H4, HH, BB*SSEQ, 0);
    gemm128<<<dim3(24, 128), 256>>>(hidden, Wih_b, b_b, (float*)xb,
                                    BB*SSEQ, H4, HH, BB*SSEQ, 0);

    for (int t = 0; t < SSEQ; t++)
        bilstm_step<<<dim3(64, 2), 256>>>(Whh_f, Whh_b, t);

    // decode x-projection: x_prev = lstm_out[:, :-1, :] (strided rows)
    gemm128<<<dim3(24, 128), 256>>>((const float*)lo, sWih, sb, (float*)dxg,
                                    BB*NSTEP, H4, D2, NSTEP, (long)SSEQ*D2);

    for (int t = 0; t < NSTEP; t++) {
        subw_step<<<128, 256>>>(sWhh, t);
        word_step<<<128, 256>>>(wWih, wWhh, wb, t);
    }

    logits_kernel<<<(BB*NSTEP + 7) / 8, 256>>>(clsW, clsb, out);
}